// round 5
// baseline (speedup 1.0000x reference)
#include <cuda_runtime.h>

#define NN  100000
#define NNP 100032          // padded to 64-row tiles (pad rows stay zero)
#define NE  1600000
#define NGR 512
#define FIN 7
#define HID 128

// ---------------- scratch (static device globals; zero-initialized) ----------------
__device__ __align__(16) float d_hw[(size_t)NNP * HID];
__device__ __align__(16) float d_h [(size_t)NNP * HID];
__device__ __align__(16) float d_t [(size_t)NN * 2];
__device__ float d_dinv[NN];
__device__ int   d_counts[NN];
__device__ int   d_cursor[NN];
__device__ int   d_off[NN + 1];
__device__ int   d_csrc[NE];
__device__ float d_cnorm[NE];
__device__ float d_pool2[NGR * 2];
__device__ int   d_gcnt[NGR];
__device__ float d_W4p[HID * 2];
__device__ float d_b4p[2];
__device__ int   d_is64_ei;
__device__ int   d_is64_batch;

__device__ __forceinline__ int load_idx(const void* p, int is64, long long i) {
    return is64 ? (int)((const long long*)p)[i] : ((const int*)p)[i];
}

// ---------------- packed f32x2 helpers (sm_103a FFMA2) ----------------
__device__ __forceinline__ unsigned long long ffma2(unsigned long long a,
                                                    unsigned long long b,
                                                    unsigned long long c) {
    unsigned long long d;
    asm("fma.rn.f32x2 %0, %1, %2, %3;" : "=l"(d) : "l"(a), "l"(b), "l"(c));
    return d;
}
__device__ __forceinline__ unsigned long long packdup(float a) {
    unsigned long long r;
    asm("mov.b64 %0, {%1, %1};" : "=l"(r) : "f"(a));
    return r;
}

// ---------------- dtype probe (int64 vs int32) ----------------
__global__ void k_detect(const void* ei, const void* batch) {
    const int* w1 = (const int*)ei;
    const int* w2 = (const int*)batch;
    int nz1 = 0, nz2 = 0;
    for (int i = 1; i < 2048; i += 2) { nz1 |= w1[i]; nz2 |= w2[i]; }
    d_is64_ei    = (nz1 == 0);
    d_is64_batch = (nz2 == 0);
}

// ---------------- init ----------------
__global__ void k_zero() {
    int i = blockIdx.x * blockDim.x + threadIdx.x;
    int stride = gridDim.x * blockDim.x;
    for (int t = i; t < NN; t += stride) { d_counts[t] = 0; d_cursor[t] = 0; }
    for (int t = i; t < NGR * 2; t += stride) d_pool2[t] = 0.f;
    for (int t = i; t < NGR; t += stride) d_gcnt[t] = 0;
}

// ---------------- degree histogram (edge destinations) ----------------
__global__ void k_hist(const void* __restrict__ ei) {
    int e = blockIdx.x * blockDim.x + threadIdx.x;
    if (e >= NE) return;
    unsigned d = (unsigned)load_idx(ei, d_is64_ei, (long long)NE + e);
    if (d < NN) atomicAdd(&d_counts[d], 1);
}

// ---------------- nodes-per-graph histogram (smem pre-aggregation) ----------------
__global__ void __launch_bounds__(256) k_bhist(const void* __restrict__ batch) {
    __shared__ int sh[NGR];
    for (int t = threadIdx.x; t < NGR; t += 256) sh[t] = 0;
    __syncthreads();
    int stride = gridDim.x * blockDim.x;
    int is64 = d_is64_batch;
    for (int i = blockIdx.x * blockDim.x + threadIdx.x; i < NN; i += stride) {
        unsigned g = (unsigned)load_idx(batch, is64, i);
        if (g < NGR) atomicAdd(&sh[g], 1);
    }
    __syncthreads();
    for (int t = threadIdx.x; t < NGR; t += 256)
        if (sh[t]) atomicAdd(&d_gcnt[t], sh[t]);
}

__global__ void k_dinv() {
    int i = blockIdx.x * blockDim.x + threadIdx.x;
    if (i < NN) d_dinv[i] = rsqrtf((float)d_counts[i] + 1.0f);   // +1 self-loop
}

// ---------------- single-block exclusive scan ----------------
__global__ void k_scan() {
    __shared__ int s[1024];
    int t = threadIdx.x;
    const int CH = (NN + 1023) / 1024;
    int lo = t * CH;
    int hi = lo + CH; if (hi > NN) hi = NN; if (lo > NN) lo = NN;
    int sum = 0;
    for (int i = lo; i < hi; i++) sum += d_counts[i];
    s[t] = sum;
    __syncthreads();
    for (int ofs = 1; ofs < 1024; ofs <<= 1) {
        int v = 0;
        if (t >= ofs) v = s[t - ofs];
        __syncthreads();
        if (t >= ofs) s[t] += v;
        __syncthreads();
    }
    int run = (t == 0) ? 0 : s[t - 1];
    for (int i = lo; i < hi; i++) { d_off[i] = run; run += d_counts[i]; }
    if (t == 1023) d_off[NN] = s[1023];
}

// ---------------- scatter edges into CSR (by dst) ----------------
__global__ void k_scatter(const void* __restrict__ ei) {
    int e = blockIdx.x * blockDim.x + threadIdx.x;
    if (e >= NE) return;
    int is64 = d_is64_ei;
    unsigned s = (unsigned)load_idx(ei, is64, e);
    unsigned d = (unsigned)load_idx(ei, is64, (long long)NE + e);
    if (s >= NN || d >= NN) return;
    int pos = d_off[d] + atomicAdd(&d_cursor[d], 1);
    d_csrc[pos] = (int)s;
    d_cnorm[pos] = d_dinv[s] * d_dinv[d];
}

// ---------------- fold: W4p = W4 @ Wlin [128,2]; b4p = b4 @ Wlin + blin ----------------
__global__ void k_fold(const float* __restrict__ W4, const float* __restrict__ b4,
                       const float* __restrict__ Wlin, const float* __restrict__ blin) {
    int j = threadIdx.x;              // 128 threads
    float s0 = 0.f, s1 = 0.f;
#pragma unroll 8
    for (int k = 0; k < HID; k++) {
        float w = W4[j * HID + k];
        s0 += w * Wlin[k * 2 + 0];
        s1 += w * Wlin[k * 2 + 1];
    }
    d_W4p[j * 2 + 0] = s0;
    d_W4p[j * 2 + 1] = s1;
    if (j < 2) {
        float s = 0.f;
        for (int k = 0; k < HID; k++) s += b4[k] * Wlin[k * 2 + j];
        d_b4p[j] = s + blin[j];
    }
}

// ---------------- layer 1 GEMM: x[N,7] @ W1[7,128] -> d_hw ----------------
__global__ void k_gemm7(const float* __restrict__ x, const float* __restrict__ W1) {
    int idx = blockIdx.x * blockDim.x + threadIdx.x;
    if (idx >= NN * HID) return;
    int n = idx >> 7, j = idx & 127;
    float acc = 0.f;
#pragma unroll
    for (int k = 0; k < FIN; k++)
        acc += __ldg(&x[n * FIN + k]) * __ldg(&W1[k * HID + j]);
    d_hw[idx] = acc;
}

// ---------------- 128x128 GEMM via FFMA2: relu(d_h)[64-tile] @ W -> d_hw -----------
// 256 threads; per thread 4 rows x 8 cols, accumulators packed as f32x2 col-pairs.
__global__ void __launch_bounds__(256) k_gemm128(const float* __restrict__ W) {
    extern __shared__ __align__(16) float smem[];
    float* hs = smem;                  // 64*128 = 32 KB
    float* ws = smem + 64 * 128;       // 128*128 = 64 KB
    const int tid = threadIdx.x;
    const int node0 = blockIdx.x * 64;

    // load full W (16384 floats) via float4
    {
        const float4* W4v = (const float4*)W;
        float4* ws4 = (float4*)ws;
#pragma unroll
        for (int i = 0; i < 16; i++) ws4[tid + i * 256] = W4v[tid + i * 256];
    }
    // load 64x128 input tile with relu
    {
        const float4* hin4 = (const float4*)(d_h + (size_t)node0 * HID);
        float4* hs4 = (float4*)hs;
#pragma unroll
        for (int i = 0; i < 8; i++) {
            float4 v = hin4[tid + i * 256];
            v.x = fmaxf(v.x, 0.f); v.y = fmaxf(v.y, 0.f);
            v.z = fmaxf(v.z, 0.f); v.w = fmaxf(v.w, 0.f);
            hs4[tid + i * 256] = v;
        }
    }
    __syncthreads();

    const int tn = tid & 15;           // 16 col groups: cols tn*8 .. +7
    const int tm = tid >> 4;           // 16 row groups: rows tm*4 .. +3
    const int c0 = tn * 8;
    const int r0 = tm * 4;

    unsigned long long acc[4][4];      // [row][colpair] : cols (c0+2p, c0+2p+1)
#pragma unroll
    for (int u = 0; u < 4; u++)
#pragma unroll
        for (int p = 0; p < 4; p++) acc[u][p] = 0ull;

#pragma unroll 2
    for (int k = 0; k < 128; k++) {
        // b: 8 cols = 4 packed pairs (two 16B shared loads, conflict-free phases)
        const ulonglong2 b01 = *(const ulonglong2*)&ws[k * 128 + c0];
        const ulonglong2 b23 = *(const ulonglong2*)&ws[k * 128 + c0 + 4];
        unsigned long long bp[4] = { b01.x, b01.y, b23.x, b23.y };
        // a: 4 broadcast scalars, duplicated into pairs
        unsigned long long ap[4];
#pragma unroll
        for (int u = 0; u < 4; u++) ap[u] = packdup(hs[(r0 + u) * 128 + k]);
#pragma unroll
        for (int u = 0; u < 4; u++)
#pragma unroll
            for (int p = 0; p < 4; p++)
                acc[u][p] = ffma2(ap[u], bp[p], acc[u][p]);
    }

#pragma unroll
    for (int u = 0; u < 4; u++) {
        ulonglong2* o = (ulonglong2*)&d_hw[(size_t)(node0 + r0 + u) * HID + c0];
        o[0] = make_ulonglong2(acc[u][0], acc[u][1]);
        o[1] = make_ulonglong2(acc[u][2], acc[u][3]);
    }
}

// ---------------- aggregation: d_h = norm-agg(d_hw) + b (warp/node, unroll 4) ------
__global__ void __launch_bounds__(128) k_agg(const float* __restrict__ b) {
    const int lane = threadIdx.x & 31;
    const int i = blockIdx.x * 4 + (threadIdx.x >> 5);
    if (i >= NN) return;
    const float4* hw4 = (const float4*)d_hw;
    const float di = d_dinv[i];
    float4 acc = hw4[(size_t)i * 32 + lane];
    float sw = di * di;
    acc.x *= sw; acc.y *= sw; acc.z *= sw; acc.w *= sw;
    int e = d_off[i];
    const int e1 = d_off[i + 1];
    for (; e + 4 <= e1; e += 4) {
        int   sa = d_csrc[e],     sb = d_csrc[e + 1];
        int   sc = d_csrc[e + 2], sd = d_csrc[e + 3];
        float wa = d_cnorm[e],     wb = d_cnorm[e + 1];
        float wc = d_cnorm[e + 2], wd = d_cnorm[e + 3];
        float4 va = hw4[(size_t)sa * 32 + lane];
        float4 vb = hw4[(size_t)sb * 32 + lane];
        float4 vc = hw4[(size_t)sc * 32 + lane];
        float4 vd = hw4[(size_t)sd * 32 + lane];
        acc.x += wa * va.x; acc.y += wa * va.y; acc.z += wa * va.z; acc.w += wa * va.w;
        acc.x += wb * vb.x; acc.y += wb * vb.y; acc.z += wb * vb.z; acc.w += wb * vb.w;
        acc.x += wc * vc.x; acc.y += wc * vc.y; acc.z += wc * vc.z; acc.w += wc * vc.w;
        acc.x += wd * vd.x; acc.y += wd * vd.y; acc.z += wd * vd.z; acc.w += wd * vd.w;
    }
    for (; e < e1; e++) {
        int s = d_csrc[e];
        float w = d_cnorm[e];
        float4 v = hw4[(size_t)s * 32 + lane];
        acc.x += w * v.x; acc.y += w * v.y; acc.z += w * v.z; acc.w += w * v.w;
    }
    float4 bv = ((const float4*)b)[lane];
    acc.x += bv.x; acc.y += bv.y; acc.z += bv.z; acc.w += bv.w;
    ((float4*)d_h)[(size_t)i * 32 + lane] = acc;
}

// ---------------- folded layer-4 GEMV: t[N,2] = relu(d_h) @ W4p (warp per node) ----
__global__ void __launch_bounds__(128) k_gemm2() {
    __shared__ float sw[HID * 2];
    const int tid = threadIdx.x;
    sw[tid] = d_W4p[tid];
    sw[tid + 128] = d_W4p[tid + 128];
    __syncthreads();

    const int lane = tid & 31;
    const int i = blockIdx.x * 4 + (tid >> 5);
    if (i >= NN) return;
    float4 a = ((const float4*)d_h)[(size_t)i * 32 + lane];
    a.x = fmaxf(a.x, 0.f); a.y = fmaxf(a.y, 0.f);
    a.z = fmaxf(a.z, 0.f); a.w = fmaxf(a.w, 0.f);
    const int j0 = lane * 4;
    float s0 = a.x * sw[(j0+0)*2]   + a.y * sw[(j0+1)*2]   + a.z * sw[(j0+2)*2]   + a.w * sw[(j0+3)*2];
    float s1 = a.x * sw[(j0+0)*2+1] + a.y * sw[(j0+1)*2+1] + a.z * sw[(j0+2)*2+1] + a.w * sw[(j0+3)*2+1];
#pragma unroll
    for (int o = 16; o > 0; o >>= 1) {
        s0 += __shfl_down_sync(0xffffffffu, s0, o);
        s1 += __shfl_down_sync(0xffffffffu, s1, o);
    }
    if (lane == 0) {
        d_t[i * 2 + 0] = s0;
        d_t[i * 2 + 1] = s1;
    }
}

// ---------------- 2-wide aggregation fused with pooling ----------------
__global__ void k_agg2pool(const void* __restrict__ batch) {
    int i = blockIdx.x * blockDim.x + threadIdx.x;
    if (i >= NN) return;
    const float2* t2 = (const float2*)d_t;
    const float di = d_dinv[i];
    float2 ti = t2[i];
    float sw = di * di;
    float a0 = sw * ti.x, a1 = sw * ti.y;
    const int e1 = d_off[i + 1];
    for (int e = d_off[i]; e < e1; e++) {
        int s = d_csrc[e];
        float w = d_cnorm[e];
        float2 ts = t2[s];
        a0 += w * ts.x; a1 += w * ts.y;
    }
    unsigned g = (unsigned)load_idx(batch, d_is64_batch, i);
    if (g >= NGR) return;
    atomicAdd(&d_pool2[g * 2 + 0], a0);
    atomicAdd(&d_pool2[g * 2 + 1], a1);
}

// ---------------- output: mean + folded bias ----------------
__global__ void k_out(float* __restrict__ out) {
    int idx = blockIdx.x * blockDim.x + threadIdx.x;
    if (idx >= NGR * 2) return;
    int g = idx >> 1, c = idx & 1;
    float cnt = fmaxf((float)d_gcnt[g], 1.0f);
    out[idx] = d_pool2[g * 2 + c] / cnt + d_b4p[c];
}

// ---------------- launch ----------------
extern "C" void kernel_launch(void* const* d_in, const int* in_sizes, int n_in,
                              void* d_out, int out_size) {
    // Resolve inputs by element count — robust to metadata ordering.
    int ix = 0, iei = 1, ibatch = 2, iW1 = 3, iWlin = 11, iblin = 12;
    int iW[3] = {5, 7, 9};
    int ib[4] = {4, 6, 8, 10};
    {
        int nW = 0, nb = 0;
        int fx = -1, fei = -1, fb = -1, fW1 = -1, fWl = -1, fbl = -1;
        int fW[3] = {-1, -1, -1}, fbias[4] = {-1, -1, -1, -1};
        for (int i = 0; i < n_in; i++) {
            switch (in_sizes[i]) {
                case 700000:  fx  = i; break;
                case 3200000: fei = i; break;
                case 100000:  fb  = i; break;
                case 896:     fW1 = i; break;
                case 16384:   if (nW < 3) fW[nW++] = i; break;
                case 128:     if (nb < 4) fbias[nb++] = i; break;
                case 256:     fWl = i; break;
                case 2:       fbl = i; break;
                default: break;
            }
        }
        if (fx >= 0 && fei >= 0 && fb >= 0 && fW1 >= 0 && fWl >= 0 && fbl >= 0 &&
            nW == 3 && nb == 4) {
            ix = fx; iei = fei; ibatch = fb; iW1 = fW1; iWlin = fWl; iblin = fbl;
            iW[0] = fW[0]; iW[1] = fW[1]; iW[2] = fW[2];
            ib[0] = fbias[0]; ib[1] = fbias[1]; ib[2] = fbias[2]; ib[3] = fbias[3];
        }
    }

    const float* x     = (const float*)d_in[ix];
    const void*  ei    = d_in[iei];
    const void*  batch = d_in[ibatch];
    const float* W1    = (const float*)d_in[iW1];
    float* out = (float*)d_out;

    cudaFuncSetAttribute(k_gemm128, cudaFuncAttributeMaxDynamicSharedMemorySize, 96 * 1024);

    k_detect<<<1, 1>>>(ei, batch);
    k_zero<<<512, 256>>>();
    k_hist<<<(NE + 255) / 256, 256>>>(ei);
    k_bhist<<<64, 256>>>(batch);
    k_dinv<<<(NN + 255) / 256, 256>>>();
    k_scan<<<1, 1024>>>();
    k_scatter<<<(NE + 255) / 256, 256>>>(ei);
    k_fold<<<1, 128>>>((const float*)d_in[iW[2]], (const float*)d_in[ib[3]],
                       (const float*)d_in[iWlin], (const float*)d_in[iblin]);

    // layer 1
    k_gemm7<<<(NN * HID + 255) / 256, 256>>>(x, W1);
    k_agg<<<NN / 4, 128>>>((const float*)d_in[ib[0]]);
    // layers 2, 3 (full 128x128, FFMA2)
    k_gemm128<<<NNP / 64, 256, 96 * 1024>>>((const float*)d_in[iW[0]]);
    k_agg<<<NN / 4, 128>>>((const float*)d_in[ib[1]]);
    k_gemm128<<<NNP / 64, 256, 96 * 1024>>>((const float*)d_in[iW[1]]);
    k_agg<<<NN / 4, 128>>>((const float*)d_in[ib[2]]);
    // folded layer 4 + pool + head
    k_gemm2<<<NN / 4, 128>>>();
    k_agg2pool<<<(NN + 255) / 256, 256>>>(batch);
    k_out<<<(NGR * 2 + 255) / 256, 256>>>(out);
}

// round 6
// speedup vs baseline: 1.2454x; 1.2454x over previous
#include <cuda_runtime.h>

#define NN  100000
#define NNP 100032          // padded to 64-row tiles (pad rows stay zero)
#define NE  1600000
#define NGR 512
#define FIN 7
#define HID 128

// ---------------- scratch (static device globals; zero-initialized) ----------------
__device__ __align__(16) float d_hw[(size_t)NNP * HID];
__device__ __align__(16) float d_h [(size_t)NNP * HID];
__device__ __align__(16) float d_ax[(size_t)NN * 8];    // aggregated x, width padded to 8
__device__ __align__(16) float d_t [(size_t)NN * 2];
__device__ float d_dinv[NN];
__device__ int   d_counts[NN];
__device__ int   d_cursor[NN];
__device__ int   d_off[NN + 1];
__device__ int   d_csrc[NE];
__device__ float d_cnorm[NE];
__device__ float d_pool2[NGR * 2];
__device__ int   d_gcnt[NGR];
__device__ float d_W4p[HID * 2];
__device__ float d_b4p[2];
__device__ int   d_is64_ei;
__device__ int   d_is64_batch;

__device__ __forceinline__ int load_idx(const void* p, int is64, long long i) {
    return is64 ? (int)((const long long*)p)[i] : ((const int*)p)[i];
}

// ---------------- dtype probe (int64 vs int32) ----------------
__global__ void k_detect(const void* ei, const void* batch) {
    const int* w1 = (const int*)ei;
    const int* w2 = (const int*)batch;
    int nz1 = 0, nz2 = 0;
    for (int i = 1; i < 2048; i += 2) { nz1 |= w1[i]; nz2 |= w2[i]; }
    d_is64_ei    = (nz1 == 0);
    d_is64_batch = (nz2 == 0);
}

// ---------------- init ----------------
__global__ void k_zero() {
    int i = blockIdx.x * blockDim.x + threadIdx.x;
    int stride = gridDim.x * blockDim.x;
    for (int t = i; t < NN; t += stride) { d_counts[t] = 0; d_cursor[t] = 0; }
    for (int t = i; t < NGR * 2; t += stride) d_pool2[t] = 0.f;
    for (int t = i; t < NGR; t += stride) d_gcnt[t] = 0;
}

// ---------------- degree histogram (edge destinations) ----------------
__global__ void k_hist(const void* __restrict__ ei) {
    int e = blockIdx.x * blockDim.x + threadIdx.x;
    if (e >= NE) return;
    unsigned d = (unsigned)load_idx(ei, d_is64_ei, (long long)NE + e);
    if (d < NN) atomicAdd(&d_counts[d], 1);
}

// ---------------- nodes-per-graph histogram (smem pre-aggregation) ----------------
__global__ void __launch_bounds__(256) k_bhist(const void* __restrict__ batch) {
    __shared__ int sh[NGR];
    for (int t = threadIdx.x; t < NGR; t += 256) sh[t] = 0;
    __syncthreads();
    int stride = gridDim.x * blockDim.x;
    int is64 = d_is64_batch;
    for (int i = blockIdx.x * blockDim.x + threadIdx.x; i < NN; i += stride) {
        unsigned g = (unsigned)load_idx(batch, is64, i);
        if (g < NGR) atomicAdd(&sh[g], 1);
    }
    __syncthreads();
    for (int t = threadIdx.x; t < NGR; t += 256)
        if (sh[t]) atomicAdd(&d_gcnt[t], sh[t]);
}

__global__ void k_dinv() {
    int i = blockIdx.x * blockDim.x + threadIdx.x;
    if (i < NN) d_dinv[i] = rsqrtf((float)d_counts[i] + 1.0f);   // +1 self-loop
}

// ---------------- single-block exclusive scan ----------------
__global__ void k_scan() {
    __shared__ int s[1024];
    int t = threadIdx.x;
    const int CH = (NN + 1023) / 1024;
    int lo = t * CH;
    int hi = lo + CH; if (hi > NN) hi = NN; if (lo > NN) lo = NN;
    int sum = 0;
    for (int i = lo; i < hi; i++) sum += d_counts[i];
    s[t] = sum;
    __syncthreads();
    for (int ofs = 1; ofs < 1024; ofs <<= 1) {
        int v = 0;
        if (t >= ofs) v = s[t - ofs];
        __syncthreads();
        if (t >= ofs) s[t] += v;
        __syncthreads();
    }
    int run = (t == 0) ? 0 : s[t - 1];
    for (int i = lo; i < hi; i++) { d_off[i] = run; run += d_counts[i]; }
    if (t == 1023) d_off[NN] = s[1023];
}

// ---------------- scatter edges into CSR (by dst) ----------------
__global__ void k_scatter(const void* __restrict__ ei) {
    int e = blockIdx.x * blockDim.x + threadIdx.x;
    if (e >= NE) return;
    int is64 = d_is64_ei;
    unsigned s = (unsigned)load_idx(ei, is64, e);
    unsigned d = (unsigned)load_idx(ei, is64, (long long)NE + e);
    if (s >= NN || d >= NN) return;
    int pos = d_off[d] + atomicAdd(&d_cursor[d], 1);
    d_csrc[pos] = (int)s;
    d_cnorm[pos] = d_dinv[s] * d_dinv[d];
}

// ---------------- fold: W4p = W4 @ Wlin [128,2]; b4p = b4 @ Wlin + blin ----------------
__global__ void k_fold(const float* __restrict__ W4, const float* __restrict__ b4,
                       const float* __restrict__ Wlin, const float* __restrict__ blin) {
    int j = threadIdx.x;              // 128 threads
    float s0 = 0.f, s1 = 0.f;
#pragma unroll 8
    for (int k = 0; k < HID; k++) {
        float w = W4[j * HID + k];
        s0 += w * Wlin[k * 2 + 0];
        s1 += w * Wlin[k * 2 + 1];
    }
    d_W4p[j * 2 + 0] = s0;
    d_W4p[j * 2 + 1] = s1;
    if (j < 2) {
        float s = 0.f;
        for (int k = 0; k < HID; k++) s += b4[k] * Wlin[k * 2 + j];
        d_b4p[j] = s + blin[j];
    }
}

// ---------------- width-7 aggregation of x: d_ax = Â x  (8 lanes per node) --------
__global__ void __launch_bounds__(128) k_aggx(const float* __restrict__ x) {
    const int sub = threadIdx.x & 7;                    // lane within node group
    const int i = blockIdx.x * 16 + (threadIdx.x >> 3); // node
    if (i >= NN) return;
    const int col = (sub < 7) ? sub : 6;                // lane 7 duplicates, discarded
    const float di = d_dinv[i];
    float acc = di * di * x[i * 7 + col];
    const int e1 = d_off[i + 1];
    for (int e = d_off[i]; e < e1; e++) {
        int s = d_csrc[e];
        float w = d_cnorm[e];
        acc += w * x[s * 7 + col];
    }
    if (sub < 7) d_ax[i * 8 + sub] = acc;
}

// ---------------- layer 1 GEMM: h1 = d_ax[N,7] @ W1[7,128] + b1 -> d_h ------------
__global__ void k_gemm7(const float* __restrict__ W1, const float* __restrict__ b1) {
    int idx = blockIdx.x * blockDim.x + threadIdx.x;
    if (idx >= NN * HID) return;
    int n = idx >> 7, j = idx & 127;
    float acc = b1[j];
#pragma unroll
    for (int k = 0; k < FIN; k++)
        acc += d_ax[n * 8 + k] * __ldg(&W1[k * HID + j]);
    d_h[idx] = acc;
}

// ---------------- 128x128 GEMM: relu(d_h)[64-tile] @ W -> d_hw (R4 version) --------
// 256 threads, 64 rows x 128 cols per block, 8x4 outputs/thread, W fully smem-resident.
__global__ void __launch_bounds__(256) k_gemm128(const float* __restrict__ W) {
    extern __shared__ __align__(16) float smem[];
    float* hs = smem;                  // 64*128 = 32 KB
    float* ws = smem + 64 * 128;       // 128*128 = 64 KB
    const int tid = threadIdx.x;
    const int node0 = blockIdx.x * 64;

    {
        const float4* W4v = (const float4*)W;
        float4* ws4 = (float4*)ws;
#pragma unroll
        for (int i = 0; i < 16; i++) ws4[tid + i * 256] = W4v[tid + i * 256];
    }
    {
        const float4* hin4 = (const float4*)(d_h + (size_t)node0 * HID);
        float4* hs4 = (float4*)hs;
#pragma unroll
        for (int i = 0; i < 8; i++) {
            float4 v = hin4[tid + i * 256];
            v.x = fmaxf(v.x, 0.f); v.y = fmaxf(v.y, 0.f);
            v.z = fmaxf(v.z, 0.f); v.w = fmaxf(v.w, 0.f);
            hs4[tid + i * 256] = v;
        }
    }
    __syncthreads();

    const int tn = tid & 31;           // col group: cols tn*4..+3
    const int tm = tid >> 5;           // row group: rows tm*8..+7
    const int c0 = tn * 4;
    const int r0 = tm * 8;
    float acc[8][4] = {};

#pragma unroll 4
    for (int k = 0; k < 128; k++) {
        float4 bv = *(const float4*)&ws[k * 128 + c0];
#pragma unroll
        for (int u = 0; u < 8; u++) {
            float a = hs[(r0 + u) * 128 + k];
            acc[u][0] += a * bv.x; acc[u][1] += a * bv.y;
            acc[u][2] += a * bv.z; acc[u][3] += a * bv.w;
        }
    }

#pragma unroll
    for (int u = 0; u < 8; u++) {
        float4 o = make_float4(acc[u][0], acc[u][1], acc[u][2], acc[u][3]);
        *(float4*)&d_hw[(size_t)(node0 + r0 + u) * HID + c0] = o;
    }
}

// ---------------- aggregation: d_h = norm-agg(d_hw) + b (warp/node, unroll 4) ------
__global__ void __launch_bounds__(128) k_agg(const float* __restrict__ b) {
    const int lane = threadIdx.x & 31;
    const int i = blockIdx.x * 4 + (threadIdx.x >> 5);
    if (i >= NN) return;
    const float4* hw4 = (const float4*)d_hw;
    const float di = d_dinv[i];
    float4 acc = hw4[(size_t)i * 32 + lane];
    float sw = di * di;
    acc.x *= sw; acc.y *= sw; acc.z *= sw; acc.w *= sw;
    int e = d_off[i];
    const int e1 = d_off[i + 1];
    for (; e + 4 <= e1; e += 4) {
        int   sa = d_csrc[e],     sb = d_csrc[e + 1];
        int   sc = d_csrc[e + 2], sd = d_csrc[e + 3];
        float wa = d_cnorm[e],     wb = d_cnorm[e + 1];
        float wc = d_cnorm[e + 2], wd = d_cnorm[e + 3];
        float4 va = hw4[(size_t)sa * 32 + lane];
        float4 vb = hw4[(size_t)sb * 32 + lane];
        float4 vc = hw4[(size_t)sc * 32 + lane];
        float4 vd = hw4[(size_t)sd * 32 + lane];
        acc.x += wa * va.x; acc.y += wa * va.y; acc.z += wa * va.z; acc.w += wa * va.w;
        acc.x += wb * vb.x; acc.y += wb * vb.y; acc.z += wb * vb.z; acc.w += wb * vb.w;
        acc.x += wc * vc.x; acc.y += wc * vc.y; acc.z += wc * vc.z; acc.w += wc * vc.w;
        acc.x += wd * vd.x; acc.y += wd * vd.y; acc.z += wd * vd.z; acc.w += wd * vd.w;
    }
    for (; e < e1; e++) {
        int s = d_csrc[e];
        float w = d_cnorm[e];
        float4 v = hw4[(size_t)s * 32 + lane];
        acc.x += w * v.x; acc.y += w * v.y; acc.z += w * v.z; acc.w += w * v.w;
    }
    float4 bv = ((const float4*)b)[lane];
    acc.x += bv.x; acc.y += bv.y; acc.z += bv.z; acc.w += bv.w;
    ((float4*)d_h)[(size_t)i * 32 + lane] = acc;
}

// ---------------- folded layer-4 GEMV: t[N,2] = relu(d_h) @ W4p (warp per node) ----
__global__ void __launch_bounds__(128) k_gemm2() {
    __shared__ float sw[HID * 2];
    const int tid = threadIdx.x;
    sw[tid] = d_W4p[tid];
    sw[tid + 128] = d_W4p[tid + 128];
    __syncthreads();

    const int lane = tid & 31;
    const int i = blockIdx.x * 4 + (tid >> 5);
    if (i >= NN) return;
    float4 a = ((const float4*)d_h)[(size_t)i * 32 + lane];
    a.x = fmaxf(a.x, 0.f); a.y = fmaxf(a.y, 0.f);
    a.z = fmaxf(a.z, 0.f); a.w = fmaxf(a.w, 0.f);
    const int j0 = lane * 4;
    float s0 = a.x * sw[(j0+0)*2]   + a.y * sw[(j0+1)*2]   + a.z * sw[(j0+2)*2]   + a.w * sw[(j0+3)*2];
    float s1 = a.x * sw[(j0+0)*2+1] + a.y * sw[(j0+1)*2+1] + a.z * sw[(j0+2)*2+1] + a.w * sw[(j0+3)*2+1];
#pragma unroll
    for (int o = 16; o > 0; o >>= 1) {
        s0 += __shfl_down_sync(0xffffffffu, s0, o);
        s1 += __shfl_down_sync(0xffffffffu, s1, o);
    }
    if (lane == 0) {
        d_t[i * 2 + 0] = s0;
        d_t[i * 2 + 1] = s1;
    }
}

// ---------------- 2-wide aggregation fused with pooling ----------------
__global__ void k_agg2pool(const void* __restrict__ batch) {
    int i = blockIdx.x * blockDim.x + threadIdx.x;
    if (i >= NN) return;
    const float2* t2 = (const float2*)d_t;
    const float di = d_dinv[i];
    float2 ti = t2[i];
    float sw = di * di;
    float a0 = sw * ti.x, a1 = sw * ti.y;
    const int e1 = d_off[i + 1];
    for (int e = d_off[i]; e < e1; e++) {
        int s = d_csrc[e];
        float w = d_cnorm[e];
        float2 ts = t2[s];
        a0 += w * ts.x; a1 += w * ts.y;
    }
    unsigned g = (unsigned)load_idx(batch, d_is64_batch, i);
    if (g >= NGR) return;
    atomicAdd(&d_pool2[g * 2 + 0], a0);
    atomicAdd(&d_pool2[g * 2 + 1], a1);
}

// ---------------- output: mean + folded bias ----------------
__global__ void k_out(float* __restrict__ out) {
    int idx = blockIdx.x * blockDim.x + threadIdx.x;
    if (idx >= NGR * 2) return;
    int g = idx >> 1, c = idx & 1;
    float cnt = fmaxf((float)d_gcnt[g], 1.0f);
    out[idx] = d_pool2[g * 2 + c] / cnt + d_b4p[c];
}

// ---------------- launch ----------------
extern "C" void kernel_launch(void* const* d_in, const int* in_sizes, int n_in,
                              void* d_out, int out_size) {
    // Resolve inputs by element count — robust to metadata ordering.
    int ix = 0, iei = 1, ibatch = 2, iW1 = 3, iWlin = 11, iblin = 12;
    int iW[3] = {5, 7, 9};
    int ib[4] = {4, 6, 8, 10};
    {
        int nW = 0, nb = 0;
        int fx = -1, fei = -1, fb = -1, fW1 = -1, fWl = -1, fbl = -1;
        int fW[3] = {-1, -1, -1}, fbias[4] = {-1, -1, -1, -1};
        for (int i = 0; i < n_in; i++) {
            switch (in_sizes[i]) {
                case 700000:  fx  = i; break;
                case 3200000: fei = i; break;
                case 100000:  fb  = i; break;
                case 896:     fW1 = i; break;
                case 16384:   if (nW < 3) fW[nW++] = i; break;
                case 128:     if (nb < 4) fbias[nb++] = i; break;
                case 256:     fWl = i; break;
                case 2:       fbl = i; break;
                default: break;
            }
        }
        if (fx >= 0 && fei >= 0 && fb >= 0 && fW1 >= 0 && fWl >= 0 && fbl >= 0 &&
            nW == 3 && nb == 4) {
            ix = fx; iei = fei; ibatch = fb; iW1 = fW1; iWlin = fWl; iblin = fbl;
            iW[0] = fW[0]; iW[1] = fW[1]; iW[2] = fW[2];
            ib[0] = fbias[0]; ib[1] = fbias[1]; ib[2] = fbias[2]; ib[3] = fbias[3];
        }
    }

    const float* x     = (const float*)d_in[ix];
    const void*  ei    = d_in[iei];
    const void*  batch = d_in[ibatch];
    float* out = (float*)d_out;

    cudaFuncSetAttribute(k_gemm128, cudaFuncAttributeMaxDynamicSharedMemorySize, 96 * 1024);

    k_detect<<<1, 1>>>(ei, batch);
    k_zero<<<512, 256>>>();
    k_hist<<<(NE + 255) / 256, 256>>>(ei);
    k_bhist<<<64, 256>>>(batch);
    k_dinv<<<(NN + 255) / 256, 256>>>();
    k_scan<<<1, 1024>>>();
    k_scatter<<<(NE + 255) / 256, 256>>>(ei);
    k_fold<<<1, 128>>>((const float*)d_in[iW[2]], (const float*)d_in[ib[3]],
                       (const float*)d_in[iWlin], (const float*)d_in[iblin]);

    // layer 1: aggregate x (width 7) first, then GEMM — Â(XW) = (ÂX)W
    k_aggx<<<(NN + 15) / 16, 128>>>(x);
    k_gemm7<<<(NN * HID + 255) / 256, 256>>>((const float*)d_in[iW1], (const float*)d_in[ib[0]]);
    // layers 2, 3 (full 128x128 FFMA GEMM + 128-wide aggregation)
    k_gemm128<<<NNP / 64, 256, 96 * 1024>>>((const float*)d_in[iW[0]]);
    k_agg<<<NN / 4, 128>>>((const float*)d_in[ib[1]]);
    k_gemm128<<<NNP / 64, 256, 96 * 1024>>>((const float*)d_in[iW[1]]);
    k_agg<<<NN / 4, 128>>>((const float*)d_in[ib[2]]);
    // folded layer 4 + pool + head
    k_gemm2<<<NN / 4, 128>>>();
    k_agg2pool<<<(NN + 255) / 256, 256>>>(batch);
    k_out<<<(NGR * 2 + 255) / 256, 256>>>(out);
}

// round 8
// speedup vs baseline: 1.5276x; 1.2266x over previous
#include <cuda_runtime.h>
#include <cuda_bf16.h>
#include <cstdint>

#define NN  100000
#define NNP 100032          // 1563 tiles of 64 rows
#define NE  1600000
#define NGR 512
#define FIN 7
#define HID 128

// ---------------- scratch (static device globals; zero-initialized) ----------------
__device__ __align__(16) float d_hw[(size_t)NNP * HID];
__device__ __align__(16) float d_h [(size_t)NNP * HID];
__device__ __align__(16) float d_ax[(size_t)NN * 8];
__device__ __align__(16) float d_t [(size_t)NN * 2];
// W hi/lo bf16, transposed [n][k], 256B rows, XOR-granule swizzled (32 KB each)
__device__ __align__(16) unsigned char d_B2hi[32768], d_B2lo[32768];
__device__ __align__(16) unsigned char d_B3hi[32768], d_B3lo[32768];
__device__ float d_dinv[NN];
__device__ int   d_counts[NN];
__device__ int   d_cursor[NN];
__device__ int   d_off[NN + 1];
__device__ int   d_csrc[NE];
__device__ float d_cnorm[NE];
__device__ float d_pool2[NGR * 2];
__device__ int   d_gcnt[NGR];
__device__ float d_W4p[HID * 2];
__device__ float d_b4p[2];
__device__ int   d_is64_ei;
__device__ int   d_is64_batch;

__device__ __forceinline__ int load_idx(const void* p, int is64, long long i) {
    return is64 ? (int)((const long long*)p)[i] : ((const int*)p)[i];
}

// ---------------- bf16 split helpers ----------------
__device__ __forceinline__ unsigned short bfh(float v) {
    return __bfloat16_as_ushort(__float2bfloat16(v));
}
__device__ __forceinline__ float bf2f(unsigned short u) {
    return __bfloat162float(__ushort_as_bfloat16(u));
}

// swizzled byte offset within a [rows][256B] bf16 image: 16B granules XORed by row&7
__device__ __forceinline__ unsigned sw_off(int row, int kb) {
    return (unsigned)(row * 256) + ((((unsigned)kb >> 4) ^ ((unsigned)row & 7u)) << 4)
         + ((unsigned)kb & 15u);
}

// ---------------- mma.sync m16n8k16 bf16 (arch-agnostic PTX, lowers to HMMA) -------
__device__ __forceinline__ void mma_bf16(float c[4], const unsigned a[4], const unsigned b[2]) {
    asm volatile(
        "mma.sync.aligned.m16n8k16.row.col.f32.bf16.bf16.f32 "
        "{%0,%1,%2,%3}, {%4,%5,%6,%7}, {%8,%9}, {%0,%1,%2,%3};"
        : "+f"(c[0]), "+f"(c[1]), "+f"(c[2]), "+f"(c[3])
        : "r"(a[0]), "r"(a[1]), "r"(a[2]), "r"(a[3]), "r"(b[0]), "r"(b[1]));
}

// ---------------- dtype probe (int64 vs int32), warp-parallel ----------------
__global__ void k_detect(const void* ei, const void* batch) {
    const int* w1 = (const int*)ei;
    const int* w2 = (const int*)batch;
    int lane = threadIdx.x;
    int nz1 = 0, nz2 = 0;
    for (int i = 2 * lane + 1; i < 4096; i += 64) { nz1 |= w1[i]; nz2 |= w2[i]; }
    nz1 = __reduce_or_sync(0xffffffffu, nz1);
    nz2 = __reduce_or_sync(0xffffffffu, nz2);
    if (lane == 0) { d_is64_ei = (nz1 == 0); d_is64_batch = (nz2 == 0); }
}

// ---------------- init ----------------
__global__ void k_zero() {
    int i = blockIdx.x * blockDim.x + threadIdx.x;
    int stride = gridDim.x * blockDim.x;
    for (int t = i; t < NN; t += stride) { d_counts[t] = 0; d_cursor[t] = 0; }
    for (int t = i; t < NGR * 2; t += stride) d_pool2[t] = 0.f;
    for (int t = i; t < NGR; t += stride) d_gcnt[t] = 0;
}

// ---------------- degree histogram (edge destinations) ----------------
__global__ void k_hist(const void* __restrict__ ei) {
    int e = blockIdx.x * blockDim.x + threadIdx.x;
    if (e >= NE) return;
    unsigned d = (unsigned)load_idx(ei, d_is64_ei, (long long)NE + e);
    if (d < NN) atomicAdd(&d_counts[d], 1);
}

// ---------------- nodes-per-graph histogram (smem pre-aggregation) ----------------
__global__ void __launch_bounds__(256) k_bhist(const void* __restrict__ batch) {
    __shared__ int sh[NGR];
    for (int t = threadIdx.x; t < NGR; t += 256) sh[t] = 0;
    __syncthreads();
    int stride = gridDim.x * blockDim.x;
    int is64 = d_is64_batch;
    for (int i = blockIdx.x * blockDim.x + threadIdx.x; i < NN; i += stride) {
        unsigned g = (unsigned)load_idx(batch, is64, i);
        if (g < NGR) atomicAdd(&sh[g], 1);
    }
    __syncthreads();
    for (int t = threadIdx.x; t < NGR; t += 256)
        if (sh[t]) atomicAdd(&d_gcnt[t], sh[t]);
}

__global__ void k_dinv() {
    int i = blockIdx.x * blockDim.x + threadIdx.x;
    if (i < NN) d_dinv[i] = rsqrtf((float)d_counts[i] + 1.0f);
}

// ---------------- single-block exclusive scan ----------------
__global__ void k_scan() {
    __shared__ int s[1024];
    int t = threadIdx.x;
    const int CH = (NN + 1023) / 1024;
    int lo = t * CH;
    int hi = lo + CH; if (hi > NN) hi = NN; if (lo > NN) lo = NN;
    int sum = 0;
    for (int i = lo; i < hi; i++) sum += d_counts[i];
    s[t] = sum;
    __syncthreads();
    for (int ofs = 1; ofs < 1024; ofs <<= 1) {
        int v = 0;
        if (t >= ofs) v = s[t - ofs];
        __syncthreads();
        if (t >= ofs) s[t] += v;
        __syncthreads();
    }
    int run = (t == 0) ? 0 : s[t - 1];
    for (int i = lo; i < hi; i++) { d_off[i] = run; run += d_counts[i]; }
    if (t == 1023) d_off[NN] = s[1023];
}

// ---------------- scatter edges into CSR (by dst) ----------------
__global__ void k_scatter(const void* __restrict__ ei) {
    int e = blockIdx.x * blockDim.x + threadIdx.x;
    if (e >= NE) return;
    int is64 = d_is64_ei;
    unsigned s = (unsigned)load_idx(ei, is64, e);
    unsigned d = (unsigned)load_idx(ei, is64, (long long)NE + e);
    if (s >= NN || d >= NN) return;
    int pos = d_off[d] + atomicAdd(&d_cursor[d], 1);
    d_csrc[pos] = (int)s;
    d_cnorm[pos] = d_dinv[s] * d_dinv[d];
}

// ---------------- fold: W4p = W4 @ Wlin; b4p = b4 @ Wlin + blin ----------------
__global__ void k_fold(const float* __restrict__ W4, const float* __restrict__ b4,
                       const float* __restrict__ Wlin, const float* __restrict__ blin) {
    int j = threadIdx.x;
    float s0 = 0.f, s1 = 0.f;
#pragma unroll 8
    for (int k = 0; k < HID; k++) {
        float w = W4[j * HID + k];
        s0 += w * Wlin[k * 2 + 0];
        s1 += w * Wlin[k * 2 + 1];
    }
    d_W4p[j * 2 + 0] = s0;
    d_W4p[j * 2 + 1] = s1;
    if (j < 2) {
        float s = 0.f;
        for (int k = 0; k < HID; k++) s += b4[k] * Wlin[k * 2 + j];
        d_b4p[j] = s + blin[j];
    }
}

// ---------------- W -> split-bf16, transposed [n][k], swizzled ----------------
__global__ void k_wconv(const float* __restrict__ W, int sel) {
    int idx = blockIdx.x * blockDim.x + threadIdx.x;
    if (idx >= HID * 64) return;
    int n = idx >> 6;
    int kp2 = idx & 63;                 // k-pair index; k = kp2*2
    int k = kp2 * 2;
    float v0 = W[k * HID + n];
    float v1 = W[(k + 1) * HID + n];
    unsigned short h0 = bfh(v0), h1 = bfh(v1);
    unsigned short l0 = bfh(v0 - bf2f(h0)), l1 = bfh(v1 - bf2f(h1));
    unsigned off = sw_off(n, k * 2);    // kb = k*2 bytes
    unsigned char* bh = sel ? d_B3hi : d_B2hi;
    unsigned char* bl = sel ? d_B3lo : d_B2lo;
    *(unsigned*)(bh + off) = (unsigned)h0 | ((unsigned)h1 << 16);
    *(unsigned*)(bl + off) = (unsigned)l0 | ((unsigned)l1 << 16);
}

// ---------------- width-7 aggregation of x: d_ax = Â x ----------------
__global__ void __launch_bounds__(128) k_aggx(const float* __restrict__ x) {
    const int sub = threadIdx.x & 7;
    const int i = blockIdx.x * 16 + (threadIdx.x >> 3);
    if (i >= NN) return;
    const int col = (sub < 7) ? sub : 6;
    const float di = d_dinv[i];
    float acc = di * di * x[i * 7 + col];
    const int e1 = d_off[i + 1];
    for (int e = d_off[i]; e < e1; e++) {
        int s = d_csrc[e];
        float w = d_cnorm[e];
        acc += w * x[s * 7 + col];
    }
    if (sub < 7) d_ax[i * 8 + sub] = acc;
}

// ---------------- layer 1: h1 = ax @ W1 + b1 -> d_h (fp32) ----------------
__global__ void k_gemm7(const float* __restrict__ W1, const float* __restrict__ b1) {
    int idx = blockIdx.x * blockDim.x + threadIdx.x;
    if (idx >= NN * HID) return;
    int n = idx >> 7, j = idx & 127;
    float acc = b1[j];
#pragma unroll
    for (int k = 0; k < FIN; k++)
        acc += d_ax[n * 8 + k] * __ldg(&W1[k * HID + j]);
    d_h[idx] = acc;
}

// ---------------- 128x128 GEMM via mma.sync bf16x3: relu(d_h) @ W -> d_hw ----------
// 256 threads, 64 rows x 128 cols/block; 8 warps of 32x32 tiles.
__global__ void __launch_bounds__(256) k_gemm128(int sel) {
    extern __shared__ __align__(16) unsigned char smem[];
    unsigned char* As_hi = smem;            // 64*256 = 16 KB
    unsigned char* As_lo = smem + 16384;
    unsigned char* Bs_hi = smem + 32768;    // 128*256 = 32 KB
    unsigned char* Bs_lo = smem + 65536;
    const int tid = threadIdx.x;
    const int node0 = blockIdx.x * 64;

    // copy W tiles (already swizzled image)
    {
        const uint4* bh = (const uint4*)(sel ? d_B3hi : d_B2hi);
        const uint4* bl = (const uint4*)(sel ? d_B3lo : d_B2lo);
        uint4* sh = (uint4*)Bs_hi;
        uint4* sl = (uint4*)Bs_lo;
#pragma unroll
        for (int i = 0; i < 8; i++) sh[tid + i * 256] = bh[tid + i * 256];
#pragma unroll
        for (int i = 0; i < 8; i++) sl[tid + i * 256] = bl[tid + i * 256];
    }
    // load A tile: relu + bf16 split + swizzled store
    {
        const float4* hin4 = (const float4*)(d_h + (size_t)node0 * HID);
#pragma unroll
        for (int it = 0; it < 8; it++) {
            int li = tid + it * 256;        // float4 index within 64x128 tile
            int row = li >> 5;
            int c4 = li & 31;
            float4 v = hin4[li];
            v.x = fmaxf(v.x, 0.f); v.y = fmaxf(v.y, 0.f);
            v.z = fmaxf(v.z, 0.f); v.w = fmaxf(v.w, 0.f);
            unsigned short h0 = bfh(v.x), h1 = bfh(v.y), h2 = bfh(v.z), h3 = bfh(v.w);
            unsigned short l0 = bfh(v.x - bf2f(h0)), l1 = bfh(v.y - bf2f(h1));
            unsigned short l2 = bfh(v.z - bf2f(h2)), l3 = bfh(v.w - bf2f(h3));
            unsigned long long ph = (unsigned long long)((unsigned)h0 | ((unsigned)h1 << 16))
                                  | ((unsigned long long)((unsigned)h2 | ((unsigned)h3 << 16)) << 32);
            unsigned long long pl = (unsigned long long)((unsigned)l0 | ((unsigned)l1 << 16))
                                  | ((unsigned long long)((unsigned)l2 | ((unsigned)l3 << 16)) << 32);
            unsigned off = sw_off(row, c4 * 8);   // kb = c0*2 = c4*8 bytes (8B aligned)
            *(unsigned long long*)(As_hi + off) = ph;
            *(unsigned long long*)(As_lo + off) = pl;
        }
    }
    __syncthreads();

    const int w = tid >> 5, lane = tid & 31;
    const int wm = (w & 1) * 32;
    const int wn = (w >> 1) * 32;
    const int lr = lane >> 2;           // 0..7
    const int kq = (lane & 3) * 4;      // byte offset within 16B granule

    float c[2][4][4] = {};

#pragma unroll
    for (int ks = 0; ks < 8; ks++) {
        const int kb0 = ks * 32;
        unsigned ah[2][4], al[2][4], bh[4][2], bl[4][2];
#pragma unroll
        for (int mt = 0; mt < 2; mt++) {
            int r = wm + mt * 16 + lr;
            ah[mt][0] = *(const unsigned*)(As_hi + sw_off(r,     kb0 + kq));
            ah[mt][1] = *(const unsigned*)(As_hi + sw_off(r + 8, kb0 + kq));
            ah[mt][2] = *(const unsigned*)(As_hi + sw_off(r,     kb0 + 16 + kq));
            ah[mt][3] = *(const unsigned*)(As_hi + sw_off(r + 8, kb0 + 16 + kq));
            al[mt][0] = *(const unsigned*)(As_lo + sw_off(r,     kb0 + kq));
            al[mt][1] = *(const unsigned*)(As_lo + sw_off(r + 8, kb0 + kq));
            al[mt][2] = *(const unsigned*)(As_lo + sw_off(r,     kb0 + 16 + kq));
            al[mt][3] = *(const unsigned*)(As_lo + sw_off(r + 8, kb0 + 16 + kq));
        }
#pragma unroll
        for (int nt = 0; nt < 4; nt++) {
            int n = wn + nt * 8 + lr;
            bh[nt][0] = *(const unsigned*)(Bs_hi + sw_off(n, kb0 + kq));
            bh[nt][1] = *(const unsigned*)(Bs_hi + sw_off(n, kb0 + 16 + kq));
            bl[nt][0] = *(const unsigned*)(Bs_lo + sw_off(n, kb0 + kq));
            bl[nt][1] = *(const unsigned*)(Bs_lo + sw_off(n, kb0 + 16 + kq));
        }
#pragma unroll
        for (int mt = 0; mt < 2; mt++)
#pragma unroll
            for (int nt = 0; nt < 4; nt++) {
                mma_bf16(c[mt][nt], ah[mt], bh[nt]);
                mma_bf16(c[mt][nt], ah[mt], bl[nt]);
                mma_bf16(c[mt][nt], al[mt], bh[nt]);
            }
    }

    // epilogue: fp32 -> d_hw
#pragma unroll
    for (int mt = 0; mt < 2; mt++) {
#pragma unroll
        for (int nt = 0; nt < 4; nt++) {
            int row = node0 + wm + mt * 16 + lr;
            int col = wn + nt * 8 + (lane & 3) * 2;
            *(float2*)&d_hw[(size_t)row * HID + col] = make_float2(c[mt][nt][0], c[mt][nt][1]);
            *(float2*)&d_hw[(size_t)(row + 8) * HID + col] = make_float2(c[mt][nt][2], c[mt][nt][3]);
        }
    }
}

// ---------------- aggregation: d_h = norm-agg(d_hw) + b (warp/node, unroll 4) ------
__global__ void __launch_bounds__(128) k_agg(const float* __restrict__ b) {
    const int lane = threadIdx.x & 31;
    const int i = blockIdx.x * 4 + (threadIdx.x >> 5);
    if (i >= NN) return;
    const float4* hw4 = (const float4*)d_hw;
    const float di = d_dinv[i];
    float4 acc = hw4[(size_t)i * 32 + lane];
    float sw = di * di;
    acc.x *= sw; acc.y *= sw; acc.z *= sw; acc.w *= sw;
    int e = d_off[i];
    const int e1 = d_off[i + 1];
    for (; e + 4 <= e1; e += 4) {
        int   sa = d_csrc[e],     sb = d_csrc[e + 1];
        int   sc = d_csrc[e + 2], sd = d_csrc[e + 3];
        float wa = d_cnorm[e],     wb = d_cnorm[e + 1];
        float wc = d_cnorm[e + 2], wd = d_cnorm[e + 3];
        float4 va = hw4[(size_t)sa * 32 + lane];
        float4 vb = hw4[(size_t)sb * 32 + lane];
        float4 vc = hw4[(size_t)sc * 32 + lane];
        float4 vd = hw4[(size_t)sd * 32 + lane];
        acc.x += wa * va.x; acc.y += wa * va.y; acc.z += wa * va.z; acc.w += wa * va.w;
        acc.x += wb * vb.x; acc.y += wb * vb.y; acc.z += wb * vb.z; acc.w += wb * vb.w;
        acc.x += wc * vc.x; acc.y += wc * vc.y; acc.z += wc * vc.z; acc.w += wc * vc.w;
        acc.x += wd * vd.x; acc.y += wd * vd.y; acc.z += wd * vd.z; acc.w += wd * vd.w;
    }
    for (; e < e1; e++) {
        int s = d_csrc[e];
        float w = d_cnorm[e];
        float4 v = hw4[(size_t)s * 32 + lane];
        acc.x += w * v.x; acc.y += w * v.y; acc.z += w * v.z; acc.w += w * v.w;
    }
    float4 bv = ((const float4*)b)[lane];
    acc.x += bv.x; acc.y += bv.y; acc.z += bv.z; acc.w += bv.w;
    ((float4*)d_h)[(size_t)i * 32 + lane] = acc;
}

// ---------------- folded layer-4 GEMV: t[N,2] = relu(d_h) @ W4p ----------------
__global__ void __launch_bounds__(128) k_gemm2() {
    __shared__ float sw[HID * 2];
    const int tid = threadIdx.x;
    sw[tid] = d_W4p[tid];
    sw[tid + 128] = d_W4p[tid + 128];
    __syncthreads();

    const int lane = tid & 31;
    const int i = blockIdx.x * 4 + (tid >> 5);
    if (i >= NN) return;
    float4 a = ((const float4*)d_h)[(size_t)i * 32 + lane];
    a.x = fmaxf(a.x, 0.f); a.y = fmaxf(a.y, 0.f);
    a.z = fmaxf(a.z, 0.f); a.w = fmaxf(a.w, 0.f);
    const int j0 = lane * 4;
    float s0 = a.x * sw[(j0+0)*2]   + a.y * sw[(j0+1)*2]   + a.z * sw[(j0+2)*2]   + a.w * sw[(j0+3)*2];
    float s1 = a.x * sw[(j0+0)*2+1] + a.y * sw[(j0+1)*2+1] + a.z * sw[(j0+2)*2+1] + a.w * sw[(j0+3)*2+1];
#pragma unroll
    for (int o = 16; o > 0; o >>= 1) {
        s0 += __shfl_down_sync(0xffffffffu, s0, o);
        s1 += __shfl_down_sync(0xffffffffu, s1, o);
    }
    if (lane == 0) {
        d_t[i * 2 + 0] = s0;
        d_t[i * 2 + 1] = s1;
    }
}

// ---------------- 2-wide aggregation fused with pooling ----------------
__global__ void k_agg2pool(const void* __restrict__ batch) {
    int i = blockIdx.x * blockDim.x + threadIdx.x;
    if (i >= NN) return;
    const float2* t2 = (const float2*)d_t;
    const float di = d_dinv[i];
    float2 ti = t2[i];
    float sw = di * di;
    float a0 = sw * ti.x, a1 = sw * ti.y;
    const int e1 = d_off[i + 1];
    for (int e = d_off[i]; e < e1; e++) {
        int s = d_csrc[e];
        float w = d_cnorm[e];
        float2 ts = t2[s];
        a0 += w * ts.x; a1 += w * ts.y;
    }
    unsigned g = (unsigned)load_idx(batch, d_is64_batch, i);
    if (g >= NGR) return;
    atomicAdd(&d_pool2[g * 2 + 0], a0);
    atomicAdd(&d_pool2[g * 2 + 1], a1);
}

// ---------------- output: mean + folded bias ----------------
__global__ void k_out(float* __restrict__ out) {
    int idx = blockIdx.x * blockDim.x + threadIdx.x;
    if (idx >= NGR * 2) return;
    int g = idx >> 1, c = idx & 1;
    float cnt = fmaxf((float)d_gcnt[g], 1.0f);
    out[idx] = d_pool2[g * 2 + c] / cnt + d_b4p[c];
}

// ---------------- launch ----------------
extern "C" void kernel_launch(void* const* d_in, const int* in_sizes, int n_in,
                              void* d_out, int out_size) {
    // Resolve inputs by element count — robust to metadata ordering.
    int ix = 0, iei = 1, ibatch = 2, iW1 = 3, iWlin = 11, iblin = 12;
    int iW[3] = {5, 7, 9};
    int ib[4] = {4, 6, 8, 10};
    {
        int nW = 0, nb = 0;
        int fx = -1, fei = -1, fb = -1, fW1 = -1, fWl = -1, fbl = -1;
        int fW[3] = {-1, -1, -1}, fbias[4] = {-1, -1, -1, -1};
        for (int i = 0; i < n_in; i++) {
            switch (in_sizes[i]) {
                case 700000:  fx  = i; break;
                case 3200000: fei = i; break;
                case 100000:  fb  = i; break;
                case 896:     fW1 = i; break;
                case 16384:   if (nW < 3) fW[nW++] = i; break;
                case 128:     if (nb < 4) fbias[nb++] = i; break;
                case 256:     fWl = i; break;
                case 2:       fbl = i; break;
                default: break;
            }
        }
        if (fx >= 0 && fei >= 0 && fb >= 0 && fW1 >= 0 && fWl >= 0 && fbl >= 0 &&
            nW == 3 && nb == 4) {
            ix = fx; iei = fei; ibatch = fb; iW1 = fW1; iWlin = fWl; iblin = fbl;
            iW[0] = fW[0]; iW[1] = fW[1]; iW[2] = fW[2];
            ib[0] = fbias[0]; ib[1] = fbias[1]; ib[2] = fbias[2]; ib[3] = fbias[3];
        }
    }

    const float* x     = (const float*)d_in[ix];
    const void*  ei    = d_in[iei];
    const void*  batch = d_in[ibatch];
    float* out = (float*)d_out;

    const int GEMM_SMEM = 96 * 1024;
    cudaFuncSetAttribute(k_gemm128, cudaFuncAttributeMaxDynamicSharedMemorySize, GEMM_SMEM);

    k_detect<<<1, 32>>>(ei, batch);
    k_zero<<<512, 256>>>();
    k_hist<<<(NE + 255) / 256, 256>>>(ei);
    k_bhist<<<64, 256>>>(batch);
    k_dinv<<<(NN + 255) / 256, 256>>>();
    k_scan<<<1, 1024>>>();
    k_scatter<<<(NE + 255) / 256, 256>>>(ei);
    k_fold<<<1, 128>>>((const float*)d_in[iW[2]], (const float*)d_in[ib[3]],
                       (const float*)d_in[iWlin], (const float*)d_in[iblin]);
    k_wconv<<<32, 256>>>((const float*)d_in[iW[0]], 0);
    k_wconv<<<32, 256>>>((const float*)d_in[iW[1]], 1);

    // layer 1: (ÂX)W1 + b1 — aggregation commuted to width 7
    k_aggx<<<(NN + 15) / 16, 128>>>(x);
    k_gemm7<<<(NN * HID + 255) / 256, 256>>>((const float*)d_in[iW1], (const float*)d_in[ib[0]]);
    // layers 2, 3: tensor-core GEMM (bf16x3) + 128-wide aggregation
    k_gemm128<<<NNP / 64, 256, GEMM_SMEM>>>(0);
    k_agg<<<NN / 4, 128>>>((const float*)d_in[ib[1]]);
    k_gemm128<<<NNP / 64, 256, GEMM_SMEM>>>(1);
    k_agg<<<NN / 4, 128>>>((const float*)d_in[ib[2]]);
    // folded layer 4 + pool + head
    k_gemm2<<<NN / 4, 128>>>();
    k_agg2pool<<<(NN + 255) / 256, 256>>>(batch);
    k_out<<<(NGR * 2 + 255) / 256, 256>>>(out);
}